// round 15
// baseline (speedup 1.0000x reference)
#include <cuda_runtime.h>
#include <cstdint>

#define NB   32
#define H    1024
#define W    1024
#define BH   73
#define BW   73
#define BS   14                  // block stride = 16 - 3 + 1
#define NROWS (NB*BH)            // 2336 flag rows
#define TOTAL (NB*BH*BW)         // 170528

__device__ unsigned long long g_acc;       // low32: count, high32: done ctr
__device__ unsigned g_winact[NROWS * 8];   // inactive-mask per (row, warp); zero-init
                                           // (zero == "all my windows active")

// window->warp partition: warp w owns windows [first(w), first(w+1))
__host__ __device__ __forceinline__ int warp_first(int w) {
    return (w == 8) ? 73 : (120 * w + 11) / 14;
}

// ---------------------------------------------------------------------------
// Rare-path fixup (p ~ 2^-244): rebuild the whole output serially from
// g_winact (zero-init = active). Never executed in practice; correctness only.
// ---------------------------------------------------------------------------
__device__ __noinline__ void fixup(float* __restrict__ out, int total) {
    int off = 0, inoff = 0;
    for (int row = 0; row < NROWS; row++) {
        int i0 = row / BH, i1 = row - i0 * BH;
        for (int w = 0; w < 8; w++) {
            int first = warp_first(w), next = warp_first(w + 1);
            unsigned mi = g_winact[row * 8 + w];
            for (int l = 0; l < next - first; l++) {
                int t = first + l;
                if (!((mi >> l) & 1u)) {
                    int pos = off++;
                    out[3 * pos + 0] = (float)i0;
                    out[3 * pos + 1] = (float)i1;
                    out[3 * pos + 2] = (float)t;
                } else {
                    int pos = total + inoff++;
                    out[3 * pos + 0] = (float)NB;
                    out[3 * pos + 1] = (float)BH;
                    out[3 * pos + 2] = (float)BW;
                }
            }
        }
    }
}

// ---------------------------------------------------------------------------
// Single fused kernel, WARP-AUTONOMOUS fast path (no mid-kernel CTA barrier):
// One 256-thread CTA per (n, by) strip.
//  - warp w<7 loads probe chunks 30w+lane (overlap 2 with next warp);
//    warp 7 loads 210+lane and additionally ballots chunks 224+lane.
//  - every window's 3 fully-contained chunks sit inside ONE warp's ballot
//    word -> per-warp shift/mask eval, no smem, no cross-warp sync.
//  - speculative output triples (prefix 73*cta) written in the load shadow.
//  - undecided windows (p=2^-12): the owning warp recomputes the true 16x16
//    max directly from gmem (warp-local).
//  - lane0 of each warp: one shared atomic pack; 8th arrival does the single
//    global release-atomic; global-last writes count, (never) fixup, resets.
// ---------------------------------------------------------------------------
__global__ __launch_bounds__(256) void fused_kernel(const float* __restrict__ mask,
                                                    float* __restrict__ out,
                                                    int count_idx) {
    const int cta = blockIdx.x;          // n*BH + by
    const int n  = cta / BH;
    const int by = cta - n * BH;
    const int t  = threadIdx.x;
    const int w  = t >> 5, lane = t & 31;

    __shared__ unsigned s_pack;
    if (t == 0) s_pack = 0u;
    __syncthreads();                      // only barrier; before the load

    const float4* base4 = (const float4*)(mask + (size_t)n * H * W);
    const float4* rowp  = base4 + (size_t)(by * BS) * (W / 4);

    // ---- probe loads (warp 7 issues two, back-to-back) ----
    const int c1 = (w < 7) ? (30 * w + lane) : (210 + lane);
    float4 v = rowp[c1];
    float4 v2 = make_float4(0.f, 0.f, 0.f, 0.f);
    if (w == 7) v2 = rowp[224 + lane];

    // ---- speculative output triples in the load shadow ----
    if (t < 3 * BW) {
        int c = t - (t / 3) * 3;
        int p = t / 3;
        float val = (c == 0) ? (float)n : (c == 1) ? (float)by : (float)p;
        out[(size_t)cta * (3 * BW) + t] = val;
    }

    // ---- chunk-hot ballots (warp-local) ----
    int hot1 = (v.x > 0.5f) | (v.y > 0.5f) | (v.z > 0.5f) | (v.w > 0.5f);
    unsigned B1 = __ballot_sync(0xffffffffu, hot1);
    unsigned B2 = 0u;
    if (w == 7) {                         // warp-uniform branch
        int hot2 = (v2.x > 0.5f) | (v2.y > 0.5f) | (v2.z > 0.5f) | (v2.w > 0.5f);
        B2 = __ballot_sync(0xffffffffu, hot2);
    }

    // ---- per-warp window eval: lane l -> window first(w)+l ----
    const int first = warp_first(w);
    const int next  = warp_first(w + 1);
    const int tw = first + lane;
    const int valid = tw < next;          // 8..13 windows per warp
    int flag = 0;
    if (valid) {
        int jlo = (14 * tw + 2) >> 2;     // first fully-contained chunk (span 3)
        unsigned B; int rel;
        if (w < 7)           { B = B1; rel = jlo - 30 * w; }
        else if (jlo >= 242) { B = B2; rel = jlo - 224;    }
        else                 { B = B1; rel = jlo - 210;    }
        flag = ((B >> rel) & 7u) != 0u;
    }
    unsigned act = __ballot_sync(0xffffffffu, valid && flag);
    unsigned und = __ballot_sync(0xffffffffu, valid && !flag);
    int cnt = __popc(act);
    unsigned inact = 0u;

    if (und) {                            // rare, warp-uniform, warp-local
        const float* mbase = mask + (size_t)n * H * W;
        const int r0 = by * BS - 1;       // may be -1 (zero pad)
        for (unsigned m = und; m; m &= m - 1) {
            int l0;
            asm("bfind.u32 %0, %1;" : "=r"(l0) : "r"(m & (0u - m)));  // ctz
            int tu = first + l0;
            int c0 = 14 * tu - 1;         // may be -1 only for tu==0
            int r  = r0 + (lane & 15);    // 16 rows, <= 1022
            int cb = c0 + ((lane >> 4) << 3);
            float mx = 0.f;
#pragma unroll
            for (int k = 0; k < 8; k++) {
                int c = cb + k;           // <= 1022
                if (r >= 0 && c >= 0) mx = fmaxf(mx, mbase[(size_t)r * W + c]);
            }
#pragma unroll
            for (int s = 16; s; s >>= 1) mx = fmaxf(mx, __shfl_xor_sync(0xffffffffu, mx, s));
            if (mx > 0.5f) cnt++;
            else inact |= 1u << l0;
        }
    }

    if (lane != 0) return;                // warp-decoupled retirement

    if (inact) {                          // never in practice
        g_winact[cta * 8 + w] = inact;
        __threadfence();
    }
    unsigned old = atomicAdd(&s_pack, (unsigned)cnt | (1u << 16));
    if ((old >> 16) != 7u) return;        // not the CTA's last warp

    unsigned tot = (old & 0xffffu) + (unsigned)cnt;
    unsigned long long add = (unsigned long long)tot | (1ull << 32);
    unsigned long long o2;
    asm volatile("atom.add.release.gpu.u64 %0, [%1], %2;"
                 : "=l"(o2) : "l"(&g_acc), "l"(add) : "memory");
    if ((unsigned)(o2 >> 32) == NROWS - 1) {          // global-last CTA
        unsigned grand = (unsigned)(o2 & 0xffffffffu) + tot;
        if (count_idx >= 0) out[count_idx] = (float)grand;
        if (grand != TOTAL) {
            asm volatile("fence.acquire.gpu;" ::: "memory");
            fixup(out, (int)grand);
        }
        g_acc = 0ull;                                 // reset for next replay
    }
}

extern "C" void kernel_launch(void* const* d_in, const int* in_sizes, int n_in,
                              void* d_out, int out_size) {
    const float* mask = (const float*)d_in[0];
    float* out = (float*)d_out;

    int count_idx = (out_size > 3 * TOTAL) ? (out_size - 1) : -1;

    fused_kernel<<<NROWS, 256>>>(mask, out, count_idx);
}